// round 1
// baseline (speedup 1.0000x reference)
#include <cuda_runtime.h>
#include <math.h>

// NNLS PGD step:
//   new_X = relu(th1 @ Y + weight)
//   Y_new = new_X + (k-1)/(k+2) * (new_X - X_old)
// Outputs (flattened tuple): [Y_new (K*B) | new_X (K*B) | k+1 (1) | weight (K*B)]
//
// th1: [K,K] f32 row-major, Y/X_old/weight: [K,B] f32 row-major.

#define BM 128
#define BN 128
#define BK 8
#define TM 8
#define TN 8

__global__ __launch_bounds__(256, 2) void nnls_gemm_fused(
    const float* __restrict__ A,      // th1 [K,K]
    const float* __restrict__ Bm,     // Y   [K,N]
    const float* __restrict__ Xold,   // [K,N]
    const float* __restrict__ W,      // [K,N]
    const int*   __restrict__ kptr,   // scalar iteration counter
    float* __restrict__ Ynew,         // [K,N]
    float* __restrict__ newX,         // [K,N] (may be null)
    int K, int N)
{
    __shared__ float As[BK][BM];   // transposed A tile: As[k][m]
    __shared__ float Bs[BK][BN];   // Bs[k][n]

    const int tid = threadIdx.x;
    const int tx  = tid & 15;      // 0..15 -> column group
    const int ty  = tid >> 4;      // 0..15 -> row group
    const int bm  = blockIdx.y * BM;
    const int bn  = blockIdx.x * BN;

    // A tile load mapping: 128 rows x 8 cols = 1024 floats = 256 float4
    const int a_row  = tid >> 1;          // 0..127
    const int a_col4 = (tid & 1) * 4;     // 0 or 4
    // B tile load mapping: 8 rows x 128 cols = 256 float4
    const int b_row  = tid >> 5;          // 0..7
    const int b_col  = (tid & 31) * 4;    // 0..124

    float acc[TM][TN];
    #pragma unroll
    for (int i = 0; i < TM; i++)
        #pragma unroll
        for (int j = 0; j < TN; j++)
            acc[i][j] = 0.0f;

    const float* a_ptr = A + (size_t)(bm + a_row) * K + a_col4;
    const float* b_ptr = Bm + (size_t)b_row * N + bn + b_col;

    for (int kt = 0; kt < K; kt += BK) {
        float4 av = *(const float4*)(a_ptr + kt);
        As[a_col4 + 0][a_row] = av.x;
        As[a_col4 + 1][a_row] = av.y;
        As[a_col4 + 2][a_row] = av.z;
        As[a_col4 + 3][a_row] = av.w;

        float4 bv = *(const float4*)(b_ptr + (size_t)kt * N);
        *(float4*)&Bs[b_row][b_col] = bv;

        __syncthreads();

        #pragma unroll
        for (int k = 0; k < BK; k++) {
            float4 a0 = *(const float4*)&As[k][ty * TM];
            float4 a1 = *(const float4*)&As[k][ty * TM + 4];
            float4 b0 = *(const float4*)&Bs[k][tx * TN];
            float4 b1 = *(const float4*)&Bs[k][tx * TN + 4];
            float a[TM] = {a0.x, a0.y, a0.z, a0.w, a1.x, a1.y, a1.z, a1.w};
            float b[TN] = {b0.x, b0.y, b0.z, b0.w, b1.x, b1.y, b1.z, b1.w};
            #pragma unroll
            for (int i = 0; i < TM; i++)
                #pragma unroll
                for (int j = 0; j < TN; j++)
                    acc[i][j] = fmaf(a[i], b[j], acc[i][j]);
        }
        __syncthreads();
    }

    // Epilogue: new_X = relu(acc + W); Y_new = new_X*(1+m) - m*X_old
    const int kk = *kptr;
    const float mom = (float)(kk - 1) / (float)(kk + 2);

    #pragma unroll
    for (int i = 0; i < TM; i++) {
        const int row = bm + ty * TM + i;
        const size_t base = (size_t)row * N + bn + tx * TN;
        #pragma unroll
        for (int j4 = 0; j4 < TN; j4 += 4) {
            float4 wv = *(const float4*)(W + base + j4);
            float4 xo = *(const float4*)(Xold + base + j4);
            float4 nx, yn;
            nx.x = fmaxf(acc[i][j4 + 0] + wv.x, 0.0f);
            nx.y = fmaxf(acc[i][j4 + 1] + wv.y, 0.0f);
            nx.z = fmaxf(acc[i][j4 + 2] + wv.z, 0.0f);
            nx.w = fmaxf(acc[i][j4 + 3] + wv.w, 0.0f);
            yn.x = nx.x + mom * (nx.x - xo.x);
            yn.y = nx.y + mom * (nx.y - xo.y);
            yn.z = nx.z + mom * (nx.z - xo.z);
            yn.w = nx.w + mom * (nx.w - xo.w);
            *(float4*)(Ynew + base + j4) = yn;
            if (newX) *(float4*)(newX + base + j4) = nx;
        }
    }
}

__global__ void nnls_write_meta(float* out, const int* kptr) {
    out[0] = (float)(*kptr + 1);
}

extern "C" void kernel_launch(void* const* d_in, const int* in_sizes, int n_in,
                              void* d_out, int out_size) {
    const float* th1  = (const float*)d_in[0];
    const float* Y    = (const float*)d_in[1];
    const float* Xold = (const float*)d_in[2];
    const int*   kptr = (const int*)  d_in[3];
    const float* W    = (const float*)d_in[4];

    // Derive K, B from input sizes (th1 is K x K, Y is K x B)
    int K = 1;
    while ((long long)K * K < (long long)in_sizes[0]) K <<= 1;
    const int N = in_sizes[1] / K;
    const size_t KB = (size_t)K * N;

    float* out  = (float*)d_out;
    float* Ynew = out;
    float* newX = ((size_t)out_size >= 2 * KB) ? out + KB : nullptr;

    dim3 grid(N / BN, K / BM);
    nnls_gemm_fused<<<grid, 256>>>(th1, Y, Xold, W, kptr, Ynew, newX, K, N);

    if ((size_t)out_size >= 3 * KB + 1) {
        nnls_write_meta<<<1, 1>>>(out + 2 * KB, kptr);
        cudaMemcpyAsync(out + 2 * KB + 1, W, KB * sizeof(float),
                        cudaMemcpyDeviceToDevice);
    }
}